// round 9
// baseline (speedup 1.0000x reference)
#include <cuda_runtime.h>
#include <cuda_fp16.h>
#include <math.h>
#include <stdint.h>

#define NN 50000
#define NE 100000
#define NRL 500
#define NB 64
#define FF 768
#define FV 2304
#define NMEGA (4 * FF)  // 3072
#define ENC_NEG_INF 0x007FFFFFu

// ---------------- scratch (static device memory; no allocations) ------------
__device__ __align__(16) float g_big0[NN * FF];   // hl
__device__ __align__(16) float g_big1[NN * FF];   // hs
__device__ __align__(16) float g_big2[NN * FF];   // t1 -> msg accum / ent_emb
__device__ __align__(16) float g_big3[NN * FF];   // t2
__device__ __align__(16) __half g_Ahf[NN * FF];   // fp16 entities -> then glh
__device__ __align__(16) __half g_grh[NN * FF];   // fp16 gr
__device__ __align__(16) __half g_Bhf[NMEGA * FF];  // [3072,768] fused W^T fp16
__device__ __align__(16) __half g_WrH[FF * FF];     // fp16 inj_Wr
__device__ __align__(16) __half g_EncT[2 * FF * FF];  // fp16 [encWl|encWr]^T
__device__ __align__(16) float g_P[2 * FF * FF];  // P1 | P2
__device__ __align__(16) float g_q3[3 * NB * FF];  // hq | Gql | Gqr
__device__ __align__(16) float g_ge[NRL * FF];
__device__ float g_logit[NE];
__device__ unsigned g_nmax[NN];
__device__ float g_nsum[NN];
__device__ float g_gate[NN];
__device__ unsigned g_gmax[NB];
__device__ float g_gsum[NB];
__device__ __align__(16) float g_pool[NB * FF];

// ---------------- helpers ----------------------------------------------------
__device__ __forceinline__ float lrelu(float x) { return x > 0.f ? x : 0.2f * x; }

__device__ __forceinline__ unsigned f2ord(float f) {
    unsigned u = __float_as_uint(f);
    return (u & 0x80000000u) ? ~u : (u | 0x80000000u);
}
__device__ __forceinline__ float ord2f(unsigned u) {
    return (u & 0x80000000u) ? __uint_as_float(u & 0x7FFFFFFFu) : __uint_as_float(~u);
}

__device__ __forceinline__ unsigned cat_h(__half a, __half b) {
    return (unsigned)__half_as_ushort(a) | ((unsigned)__half_as_ushort(b) << 16);
}
__device__ __forceinline__ float2 h2f2(unsigned u) {
    __half2 h = *(__half2*)&u;
    return __half22float2(h);
}

__device__ __forceinline__ uint32_t smem_u32(const void* p) {
    uint32_t a;
    asm("{ .reg .u64 t; cvta.to.shared.u64 t, %1; cvt.u32.u64 %0, t; }" : "=r"(a) : "l"(p));
    return a;
}

__device__ __forceinline__ void ldsm4(unsigned* r, uint32_t addr) {
    asm volatile("ldmatrix.sync.aligned.m8n8.x4.shared.b16 {%0,%1,%2,%3}, [%4];"
                 : "=r"(r[0]), "=r"(r[1]), "=r"(r[2]), "=r"(r[3]) : "r"(addr));
}

__device__ __forceinline__ void mma_f16(float* d, const unsigned* a, unsigned b0,
                                        unsigned b1) {
    asm volatile(
        "mma.sync.aligned.m16n8k16.row.col.f32.f16.f16.f32 "
        "{%0,%1,%2,%3}, {%4,%5,%6,%7}, {%8,%9}, {%0,%1,%2,%3};"
        : "+f"(d[0]), "+f"(d[1]), "+f"(d[2]), "+f"(d[3])
        : "r"(a[0]), "r"(a[1]), "r"(a[2]), "r"(a[3]), "r"(b0), "r"(b1));
}

__device__ __forceinline__ void red_v4(float* p, float a, float b, float c, float d) {
    asm volatile("red.global.add.v4.f32 [%0], {%1,%2,%3,%4};"
                 :: "l"(p), "f"(a), "f"(b), "f"(c), "f"(d) : "memory");
}

// ---------------- fp16 mega GEMM -----------------------------------------------
// [o0|o1|o2|o3][M,768 each] = fp16(A)[M,768] * Bt^T (fp16), fp32 out.
// Block 128x128, warp tile 64x32 (2x4 warps), BK=64, 3 stages, 2 CTAs/SM.
#define GRS 144
#define G_ATILE 18432
#define GSTG 36864
#define NSTAGE 3
#define NCHUNK 12

__global__ __launch_bounds__(256, 2)
void gemm_mega(const __half* __restrict__ Ah, const __half* __restrict__ Bh,
               float* __restrict__ o0, float* __restrict__ o1,
               float* __restrict__ o2, float* __restrict__ o3, int M) {
    extern __shared__ char smem[];
    const uint32_t sbase = smem_u32(smem);
    const int tid = threadIdx.x;
    const int lane = tid & 31;
    const int wid = tid >> 5;
    const int wm = wid >> 2;
    const int wn = wid & 3;
    const int m0 = blockIdx.y * 128;
    const int n0 = blockIdx.x * 128;

    auto load_stage = [&](int stg, int k0) {
        uint32_t sb = sbase + stg * GSTG;
#pragma unroll
        for (int t = 0; t < 8; t++) {
            int idx = tid + t * 256;
            int r = (idx >> 3) & 127;
            int c = idx & 7;
            uint32_t dst;
            const __half* g;
            int sz = 16;
            if (idx < 1024) {
                dst = sb + r * GRS + c * 16;
                int row = m0 + r;
                if (row >= M) { row = 0; sz = 0; }
                g = Ah + (size_t)row * FF + k0 + c * 8;
            } else {
                dst = sb + G_ATILE + r * GRS + c * 16;
                g = Bh + (size_t)(n0 + r) * FF + k0 + c * 8;
            }
            asm volatile("cp.async.cg.shared.global [%0], [%1], 16, %2;"
                         :: "r"(dst), "l"(g), "r"(sz));
        }
        asm volatile("cp.async.commit_group;" ::: "memory");
    };

    float acc[4][4][4];
#pragma unroll
    for (int i = 0; i < 4; i++)
#pragma unroll
        for (int t = 0; t < 4; t++)
#pragma unroll
            for (int q = 0; q < 4; q++) acc[i][t][q] = 0.f;

    const int fr = lane & 15;
    const int fko = (lane >> 4) * 16;

    load_stage(0, 0);
    load_stage(1, 64);

#pragma unroll 1
    for (int ch = 0; ch < NCHUNK; ch++) {
        if (ch < NCHUNK - 1)
            asm volatile("cp.async.wait_group 1;" ::: "memory");
        else
            asm volatile("cp.async.wait_group 0;" ::: "memory");
        __syncthreads();
        if (ch + 2 < NCHUNK) load_stage((ch + 2) % NSTAGE, (ch + 2) * 64);

        const uint32_t sb = sbase + (ch % NSTAGE) * GSTG;
#pragma unroll
        for (int ks = 0; ks < 4; ks++) {
            unsigned ah[4][4], bh[2][4];
            const uint32_t ko = (uint32_t)(ks * 32 + fko);
#pragma unroll
            for (int i = 0; i < 4; i++) {
                uint32_t ra = sb + (uint32_t)((wm * 64 + i * 16 + fr) * GRS) + ko;
                ldsm4(ah[i], ra);
            }
#pragma unroll
            for (int j = 0; j < 2; j++) {
                uint32_t rb = sb + G_ATILE + (uint32_t)((wn * 32 + j * 16 + fr) * GRS) + ko;
                ldsm4(bh[j], rb);
            }
#pragma unroll
            for (int i = 0; i < 4; i++) {
#pragma unroll
                for (int j = 0; j < 2; j++) {
#pragma unroll
                    for (int s = 0; s < 2; s++) {
                        mma_f16(acc[i][j * 2 + s], ah[i], bh[j][s], bh[j][s + 2]);
                    }
                }
            }
        }
        __syncthreads();
    }

    const int str = blockIdx.x / 6;
    float* Cb = (str == 0) ? o0 : (str == 1) ? o1 : (str == 2) ? o2 : o3;
    const int nbase = (blockIdx.x % 6) * 128 + wn * 32;
#pragma unroll
    for (int i = 0; i < 4; i++) {
        const int r0 = m0 + wm * 64 + i * 16 + (lane >> 2);
#pragma unroll
        for (int t = 0; t < 4; t++) {
            const int col = nbase + t * 8 + (lane & 3) * 2;
            if (r0 < M)
                *(float2*)(Cb + (size_t)r0 * FF + col) =
                    make_float2(acc[i][t][0], acc[i][t][1]);
            if (r0 + 8 < M)
                *(float2*)(Cb + (size_t)(r0 + 8) * FF + col) =
                    make_float2(acc[i][t][2], acc[i][t][3]);
        }
    }
}

// ---------------- split-K small GEMM: C[M,N] += A[M,K] * B[K,N] -----------------
#define SGK 128
__global__ __launch_bounds__(256) void smallgemm(const float* __restrict__ A,
                                                 const float* __restrict__ B,
                                                 float* __restrict__ C,
                                                 int M, int N, int K) {
    __shared__ float As[32][68];
    __shared__ float Bs[32][64];
    const int tid = threadIdx.x;
    const int n0 = blockIdx.x * 64;
    const int k0 = blockIdx.y * SGK;
    const int m0 = blockIdx.z * 64;
    const int tx = tid & 15, ty = tid >> 4;
    float acc[4][4] = {};

    for (int kt = 0; kt < SGK; kt += 32) {
        __syncthreads();
#pragma unroll
        for (int i = 0; i < 2; i++) {
            int idx = tid + i * 256;
            int r = idx >> 3, c = (idx & 7) * 4;
            float4 v = (m0 + r < M)
                           ? *(const float4*)(A + (size_t)(m0 + r) * K + k0 + kt + c)
                           : make_float4(0.f, 0.f, 0.f, 0.f);
            As[c + 0][r] = v.x;
            As[c + 1][r] = v.y;
            As[c + 2][r] = v.z;
            As[c + 3][r] = v.w;
            int rb = idx >> 4, cb = (idx & 15) * 4;
            *(float4*)&Bs[rb][cb] =
                *(const float4*)(B + (size_t)(k0 + kt + rb) * N + n0 + cb);
        }
        __syncthreads();
#pragma unroll
        for (int kk = 0; kk < 32; kk++) {
            float a0 = As[kk][ty * 4 + 0], a1 = As[kk][ty * 4 + 1];
            float a2 = As[kk][ty * 4 + 2], a3 = As[kk][ty * 4 + 3];
            float4 b = *(float4*)&Bs[kk][tx * 4];
            acc[0][0] += a0 * b.x; acc[0][1] += a0 * b.y; acc[0][2] += a0 * b.z; acc[0][3] += a0 * b.w;
            acc[1][0] += a1 * b.x; acc[1][1] += a1 * b.y; acc[1][2] += a1 * b.z; acc[1][3] += a1 * b.w;
            acc[2][0] += a2 * b.x; acc[2][1] += a2 * b.y; acc[2][2] += a2 * b.z; acc[2][3] += a2 * b.w;
            acc[3][0] += a3 * b.x; acc[3][1] += a3 * b.y; acc[3][2] += a3 * b.z; acc[3][3] += a3 * b.w;
        }
    }
#pragma unroll
    for (int i = 0; i < 4; i++) {
        int r = m0 + ty * 4 + i;
        if (r < M)
            red_v4(C + (size_t)r * N + n0 + tx * 4, acc[i][0], acc[i][1], acc[i][2],
                   acc[i][3]);
    }
}

// ---------------- prep: fp32 -> fp16 convert ------------------------------------
__global__ void cvtA_kernel(const float4* __restrict__ in, uint2* __restrict__ hi,
                            int n4) {
    int i = blockIdx.x * blockDim.x + threadIdx.x;
    if (i >= n4) return;
    float4 v = in[i];
    hi[i] = make_uint2(cat_h(__float2half_rn(v.x), __float2half_rn(v.y)),
                       cat_h(__float2half_rn(v.z), __float2half_rn(v.w)));
}

// ---------------- prep: transpose-cvt of 2 weight matrices ---------------------
// Out[n][k] = (n<768 ? W0 : W1)[k][n mod 768], fp16, [1536,768]
__global__ void w2T_kernel(const float* __restrict__ W0, const float* __restrict__ W1,
                           __half* __restrict__ Out) {
    __shared__ float t[32][33];
    const int k0 = blockIdx.x * 32;
    const int n0g = blockIdx.y * 32;
    const float* W = (n0g < FF) ? W0 : W1;
    const int n0 = (n0g < FF) ? n0g : n0g - FF;
    const int tx = threadIdx.x, ty = threadIdx.y;
#pragma unroll
    for (int i = 0; i < 4; i++)
        t[ty + i * 8][tx] = W[(size_t)(k0 + ty + i * 8) * FF + n0 + tx];
    __syncthreads();
#pragma unroll
    for (int i = 0; i < 4; i++)
        Out[(size_t)(n0g + ty + i * 8) * FF + k0 + tx] = __float2half_rn(t[tx][ty + i * 8]);
}

// ---------------- prep: transpose-cvt of 4 matrices (mega weights) -------------
__global__ void wmegaT_kernel(const float* __restrict__ Wl, const float* __restrict__ Wr,
                              const float* __restrict__ P1, const float* __restrict__ P2,
                              __half* __restrict__ Bh) {
    __shared__ float t[32][33];
    const int k0 = blockIdx.x * 32;
    const int n0g = blockIdx.y * 32;
    const int sel = n0g / FF;
    const float* W = (sel == 0) ? Wl : (sel == 1) ? Wr : (sel == 2) ? P1 : P2;
    const int n0 = n0g - sel * FF;
    const int tx = threadIdx.x, ty = threadIdx.y;
#pragma unroll
    for (int i = 0; i < 4; i++)
        t[ty + i * 8][tx] = W[(size_t)(k0 + ty + i * 8) * FF + n0 + tx];
    __syncthreads();
#pragma unroll
    for (int i = 0; i < 4; i++)
        Bh[(size_t)(n0g + ty + i * 8) * FF + k0 + tx] = __float2half_rn(t[tx][ty + i * 8]);
}

// ---------------- fused injection attention + encoder-input assembly ----------
// glh[n] = fp16(a0*Gql[b] + a1*t1[n]); grh[n] = fp16(a0*Gqr[b] + a1*t2[n])
__global__ void combine2_kernel(const float* __restrict__ hl,
                                const float* __restrict__ hs,
                                const float* __restrict__ t1,
                                const float* __restrict__ t2,
                                const float* __restrict__ hqg,
                                const float* __restrict__ Gql,
                                const float* __restrict__ Gqr,
                                const int* __restrict__ batch,
                                const float* __restrict__ att,
                                __half* __restrict__ glh,
                                __half* __restrict__ grh) {
    int warp = (blockIdx.x * blockDim.x + threadIdx.x) >> 5;
    int lane = threadIdx.x & 31;
    if (warp >= NN) return;
    const int b = batch[warp];
    const float4* phl = (const float4*)(hl + (size_t)warp * FF);
    const float4* phs = (const float4*)(hs + (size_t)warp * FF);
    const float4* phq = (const float4*)(hqg + (size_t)b * FF);
    const float4* pat = (const float4*)att;

    float sq = 0.f, ss = 0.f;
#pragma unroll
    for (int i = 0; i < 6; i++) {
        int j = lane + i * 32;
        float4 l = phl[j], q = phq[j], s = phs[j], a = pat[j];
        sq += lrelu(l.x + q.x) * a.x + lrelu(l.y + q.y) * a.y +
              lrelu(l.z + q.z) * a.z + lrelu(l.w + q.w) * a.w;
        ss += lrelu(l.x + s.x) * a.x + lrelu(l.y + s.y) * a.y +
              lrelu(l.z + s.z) * a.z + lrelu(l.w + s.w) * a.w;
    }
#pragma unroll
    for (int o = 16; o > 0; o >>= 1) {
        sq += __shfl_xor_sync(0xFFFFFFFFu, sq, o);
        ss += __shfl_xor_sync(0xFFFFFFFFu, ss, o);
    }
    float m = fmaxf(sq, ss);
    float e0 = expf(sq - m), e1 = expf(ss - m);
    float inv = 1.f / (e0 + e1);
    float a0 = e0 * inv, a1 = e1 * inv;

    const float4* pt1 = (const float4*)(t1 + (size_t)warp * FF);
    const float4* pt2 = (const float4*)(t2 + (size_t)warp * FF);
    const float4* pgl = (const float4*)(Gql + (size_t)b * FF);
    const float4* pgr = (const float4*)(Gqr + (size_t)b * FF);
    uint2* ogl = (uint2*)(glh + (size_t)warp * FF);
    uint2* ogr = (uint2*)(grh + (size_t)warp * FF);
#pragma unroll
    for (int i = 0; i < 6; i++) {
        int j = lane + i * 32;
        float4 u = pt1[j], g = pgl[j];
        float gx = a0 * g.x + a1 * u.x, gy = a0 * g.y + a1 * u.y;
        float gz = a0 * g.z + a1 * u.z, gw = a0 * g.w + a1 * u.w;
        ogl[j] = make_uint2(cat_h(__float2half_rn(gx), __float2half_rn(gy)),
                            cat_h(__float2half_rn(gz), __float2half_rn(gw)));
        float4 v = pt2[j], h = pgr[j];
        float rx = a0 * h.x + a1 * v.x, ry = a0 * h.y + a1 * v.y;
        float rz = a0 * h.z + a1 * v.z, rw = a0 * h.w + a1 * v.w;
        ogr[j] = make_uint2(cat_h(__float2half_rn(rx), __float2half_rn(ry)),
                            cat_h(__float2half_rn(rz), __float2half_rn(rw)));
    }
}

// ---------------- edge logits + segment max (one warp per edge) ----------------
__global__ void edge_logit_kernel(const __half* __restrict__ glh,
                                  const __half* __restrict__ grh,
                                  const float* __restrict__ ge,
                                  const int* __restrict__ xcoo,
                                  const float* __restrict__ att,
                                  float* __restrict__ logit,
                                  unsigned* __restrict__ nmax) {
    int warp = (blockIdx.x * blockDim.x + threadIdx.x) >> 5;
    int lane = threadIdx.x & 31;
    if (warp >= NE) return;
    int src = xcoo[warp * 3 + 0];
    int rel = xcoo[warp * 3 + 1];
    int tgt = xcoo[warp * 3 + 2];
    const uint4* pt = (const uint4*)(glh + (size_t)tgt * FF);
    const uint4* pr = (const uint4*)(grh + (size_t)src * FF);
    const float4* pe = (const float4*)(ge + (size_t)rel * FF);
    const float4* pa = (const float4*)att;
    float s = 0.f;
#pragma unroll
    for (int i = 0; i < 3; i++) {
        int j = lane + i * 32;
        uint4 t8 = pt[j], r8 = pr[j];
        float4 e0 = pe[j * 2], e1 = pe[j * 2 + 1];
        float4 a0 = pa[j * 2], a1 = pa[j * 2 + 1];
        float2 t0 = h2f2(t8.x), t1 = h2f2(t8.y), t2 = h2f2(t8.z), t3 = h2f2(t8.w);
        float2 r0 = h2f2(r8.x), r1 = h2f2(r8.y), r2 = h2f2(r8.z), r3 = h2f2(r8.w);
        s += lrelu(t0.x + r0.x + e0.x) * a0.x + lrelu(t0.y + r0.y + e0.y) * a0.y +
             lrelu(t1.x + r1.x + e0.z) * a0.z + lrelu(t1.y + r1.y + e0.w) * a0.w +
             lrelu(t2.x + r2.x + e1.x) * a1.x + lrelu(t2.y + r2.y + e1.y) * a1.y +
             lrelu(t3.x + r3.x + e1.z) * a1.z + lrelu(t3.y + r3.y + e1.w) * a1.w;
    }
#pragma unroll
    for (int o = 16; o > 0; o >>= 1) s += __shfl_xor_sync(0xFFFFFFFFu, s, o);
    if (lane == 0) {
        logit[warp] = s;
        atomicMax(&nmax[tgt], f2ord(s));
    }
}

// ---------------- message scatter (unnormalized) + segment sum -----------------
__global__ void message_kernel(const int* __restrict__ xcoo,
                               const float* __restrict__ logit,
                               const unsigned* __restrict__ nmax,
                               float* __restrict__ nsum,
                               const __half* __restrict__ grh,
                               float* __restrict__ acc) {
    int warp = (blockIdx.x * blockDim.x + threadIdx.x) >> 5;
    int lane = threadIdx.x & 31;
    if (warp >= NE) return;
    int src = xcoo[warp * 3 + 0];
    int tgt = xcoo[warp * 3 + 2];
    float w = expf(logit[warp] - ord2f(nmax[tgt]));
    if (lane == 0) atomicAdd(&nsum[tgt], w);
    const uint4* pr = (const uint4*)(grh + (size_t)src * FF);
    float* pd = acc + (size_t)tgt * FF;
#pragma unroll
    for (int i = 0; i < 3; i++) {
        int j = lane + i * 32;
        uint4 v = pr[j];
        float2 f0 = h2f2(v.x), f1 = h2f2(v.y), f2 = h2f2(v.z), f3 = h2f2(v.w);
        red_v4(pd + j * 8, w * f0.x, w * f0.y, w * f1.x, w * f1.y);
        red_v4(pd + j * 8 + 4, w * f2.x, w * f2.y, w * f3.x, w * f3.y);
    }
}

// ---------------- normalize + elu + gate dot + graph max (in-place) ------------
__global__ void node_post_kernel(float* __restrict__ emb,
                                 const float* __restrict__ nsum,
                                 const float* __restrict__ gate_W,
                                 const float* __restrict__ gate_b,
                                 const int* __restrict__ batch,
                                 float* __restrict__ gate,
                                 unsigned* __restrict__ gmax) {
    int warp = (blockIdx.x * blockDim.x + threadIdx.x) >> 5;
    int lane = threadIdx.x & 31;
    if (warp >= NN) return;
    float inv = 1.f / (nsum[warp] + 1e-16f);
    float4* p = (float4*)(emb + (size_t)warp * FF);
    const float4* pw = (const float4*)gate_W;
    float s = 0.f;
#pragma unroll
    for (int i = 0; i < 6; i++) {
        int j = lane + i * 32;
        float4 v = p[j];
        v.x *= inv; v.y *= inv; v.z *= inv; v.w *= inv;
        v.x = v.x > 0.f ? v.x : expm1f(v.x);
        v.y = v.y > 0.f ? v.y : expm1f(v.y);
        v.z = v.z > 0.f ? v.z : expm1f(v.z);
        v.w = v.w > 0.f ? v.w : expm1f(v.w);
        p[j] = v;
        float4 w = pw[j];
        s += v.x * w.x + v.y * w.y + v.z * w.z + v.w * w.w;
    }
#pragma unroll
    for (int o = 16; o > 0; o >>= 1) s += __shfl_xor_sync(0xFFFFFFFFu, s, o);
    if (lane == 0) {
        float g = s + gate_b[0];
        gate[warp] = g;
        atomicMax(&gmax[batch[warp]], f2ord(g));
    }
}

// ---------------- graph softmax sum --------------------------------------------
__global__ void graph_sum_kernel(float* __restrict__ gate,
                                 const int* __restrict__ batch,
                                 const unsigned* __restrict__ gmax,
                                 float* __restrict__ gsum) {
    int n = blockIdx.x * blockDim.x + threadIdx.x;
    if (n < NN) {
        float ex = expf(gate[n] - ord2f(gmax[batch[n]]));
        gate[n] = ex;
        atomicAdd(&gsum[batch[n]], ex);
    }
}

// ---------------- pooled = segment_sum(exp*emb)/gsum (batch sorted) ------------
__global__ void pool_kernel(const float* __restrict__ emb,
                            const float* __restrict__ g,
                            const int* __restrict__ batch,
                            const float* __restrict__ gsum,
                            float* __restrict__ pool) {
    int f = blockIdx.y * 256 + threadIdx.x;
    int n0 = blockIdx.x * 1024;
    int n1 = min(n0 + 1024, NN);
    float acc = 0.f;
    int curb = batch[n0];
    for (int n = n0; n < n1; n++) {
        int b = batch[n];
        if (b != curb) {
            atomicAdd(&pool[(size_t)curb * FF + f], acc / (gsum[curb] + 1e-16f));
            acc = 0.f;
            curb = b;
        }
        acc += g[n] * emb[(size_t)n * FF + f];
    }
    atomicAdd(&pool[(size_t)curb * FF + f], acc / (gsum[curb] + 1e-16f));
}

// ---------------- init kernels --------------------------------------------------
__global__ void init_node_kernel(unsigned* nmax, float* nsum, unsigned* gmax,
                                 float* gsum, float* pool) {
    int i = blockIdx.x * blockDim.x + threadIdx.x;
    if (i < NN) {
        nmax[i] = ENC_NEG_INF;
        nsum[i] = 0.f;
    }
    if (i < NB) {
        gmax[i] = ENC_NEG_INF;
        gsum[i] = 0.f;
    }
    if (i < NB * FF) pool[i] = 0.f;
}

__global__ void zero_kernel(float4* p, int n4) {
    int i = blockIdx.x * blockDim.x + threadIdx.x;
    if (i < n4) p[i] = make_float4(0.f, 0.f, 0.f, 0.f);
}

// ---------------- launcher -------------------------------------------------------
extern "C" void kernel_launch(void* const* d_in, const int* in_sizes, int n_in,
                              void* d_out, int out_size) {
    const float* queries = (const float*)d_in[0];
    const float* entities = (const float*)d_in[1];
    const float* relations = (const float*)d_in[2];
    const int* xcoo = (const int*)d_in[3];
    const int* batch = (const int*)d_in[4];
    const float* inj_Wl = (const float*)d_in[5];
    const float* inj_Wr = (const float*)d_in[6];
    const float* inj_att = (const float*)d_in[7];
    const float* enc_Wl = (const float*)d_in[8];
    const float* enc_Wr = (const float*)d_in[9];
    const float* enc_We = (const float*)d_in[10];
    const float* enc_att = (const float*)d_in[11];
    /* d_in[12] enc_Wrel: dead code in reference */
    const float* gate_W = (const float*)d_in[13];
    const float* gate_b = (const float*)d_in[14];
    const float* vt_W = (const float*)d_in[15];
    float* out = (float*)d_out;

    float *big0, *big1, *big2, *big3, *P, *q3, *ge, *logit, *nsum, *gate, *gsum, *pool;
    __half *Ahf, *grh, *Bhf, *WrH, *EncT;
    unsigned *nmax, *gmax;
    cudaGetSymbolAddress((void**)&big0, g_big0);
    cudaGetSymbolAddress((void**)&big1, g_big1);
    cudaGetSymbolAddress((void**)&big2, g_big2);
    cudaGetSymbolAddress((void**)&big3, g_big3);
    cudaGetSymbolAddress((void**)&Ahf, g_Ahf);
    cudaGetSymbolAddress((void**)&grh, g_grh);
    cudaGetSymbolAddress((void**)&Bhf, g_Bhf);
    cudaGetSymbolAddress((void**)&WrH, g_WrH);
    cudaGetSymbolAddress((void**)&EncT, g_EncT);
    cudaGetSymbolAddress((void**)&P, g_P);
    cudaGetSymbolAddress((void**)&q3, g_q3);
    cudaGetSymbolAddress((void**)&ge, g_ge);
    cudaGetSymbolAddress((void**)&logit, g_logit);
    cudaGetSymbolAddress((void**)&nmax, g_nmax);
    cudaGetSymbolAddress((void**)&nsum, g_nsum);
    cudaGetSymbolAddress((void**)&gate, g_gate);
    cudaGetSymbolAddress((void**)&gmax, g_gmax);
    cudaGetSymbolAddress((void**)&gsum, g_gsum);
    cudaGetSymbolAddress((void**)&pool, g_pool);

    float* P1 = P;
    float* P2 = P + FF * FF;
    float* hq = q3;
    float* Gql = q3 + NB * FF;
    float* Gqr = q3 + 2 * NB * FF;

    cudaFuncSetAttribute(gemm_mega, cudaFuncAttributeMaxDynamicSharedMemorySize,
                         NSTAGE * GSTG);

    // init node/graph scratch early (independent)
    init_node_kernel<<<(NN + 255) / 256, 256>>>(nmax, nsum, gmax, gsum, pool);

    // ---- prep: fp16 entities + fp16 inj_Wr + fp16 [encWl|encWr]^T ----
    cvtA_kernel<<<(NN * FF / 4 + 255) / 256, 256>>>((const float4*)entities,
                                                    (uint2*)Ahf, NN * FF / 4);
    cvtA_kernel<<<(FF * FF / 4 + 255) / 256, 256>>>((const float4*)inj_Wr,
                                                    (uint2*)WrH, FF * FF / 4);
    w2T_kernel<<<dim3(FF / 32, 2 * FF / 32), dim3(32, 8)>>>(enc_Wl, enc_Wr, EncT);

    // ---- P1 = inj_Wr@enc_Wl, P2 = inj_Wr@enc_Wr  (fp16 tensor GEMM) ----
    gemm_mega<<<dim3(12, 6), 256, NSTAGE * GSTG>>>(WrH, EncT, P1, P2, P1, P1, FF);

    // ---- hq = queries@inj_Wr; Gql = hq@enc_Wl; Gqr = hq@enc_Wr ----
    zero_kernel<<<(3 * NB * FF / 4 + 255) / 256, 256>>>((float4*)q3, 3 * NB * FF / 4);
    smallgemm<<<dim3(FF / 64, FF / SGK, 1), 256>>>(queries, inj_Wr, hq, NB, FF, FF);
    smallgemm<<<dim3(FF / 64, FF / SGK, 1), 256>>>(hq, enc_Wl, Gql, NB, FF, FF);
    smallgemm<<<dim3(FF / 64, FF / SGK, 1), 256>>>(hq, enc_Wr, Gqr, NB, FF, FF);

    // ---- ge = relations @ enc_We ----
    zero_kernel<<<(NRL * FF / 4 + 255) / 256, 256>>>((float4*)ge, NRL * FF / 4);
    smallgemm<<<dim3(FF / 64, FF / SGK, (NRL + 63) / 64), 256>>>(relations, enc_We, ge,
                                                                 NRL, FF, FF);

    // ---- fused mega weights [Wl | Wr | P1 | P2] -> Bhf fp16 ----
    wmegaT_kernel<<<dim3(FF / 32, NMEGA / 32), dim3(32, 8)>>>(inj_Wl, inj_Wr, P1, P2,
                                                              Bhf);

    // ---- mega GEMM: fp16(E) @ Bhf^T -> hl, hs, t1, t2 ----
    gemm_mega<<<dim3(NMEGA / 128, (NN + 127) / 128), 256, NSTAGE * GSTG>>>(
        Ahf, Bhf, big0, big1, big2, big3, NN);

    // ---- injection attention + assembly (fp16 gl/gr; Ahf reused as glh) ----
    combine2_kernel<<<(NN * 32 + 255) / 256, 256>>>(big0, big1, big2, big3, hq, Gql,
                                                    Gqr, batch, inj_att, Ahf, grh);

    // ---- edge logits + segment max ----
    edge_logit_kernel<<<(NE * 32 + 255) / 256, 256>>>(Ahf, grh, ge, xcoo, enc_att,
                                                      logit, nmax);

    // ---- unnormalized message scatter + segment sum ----
    zero_kernel<<<(NN * FF / 4 + 255) / 256, 256>>>((float4*)big2, NN * FF / 4);
    message_kernel<<<(NE * 32 + 255) / 256, 256>>>(xcoo, logit, nmax, nsum, grh, big2);

    // ---- normalize + elu + gate + graph max ----
    node_post_kernel<<<(NN * 32 + 255) / 256, 256>>>(big2, nsum, gate_W, gate_b,
                                                     batch, gate, gmax);

    graph_sum_kernel<<<(NN + 255) / 256, 256>>>(gate, batch, gmax, gsum);

    pool_kernel<<<dim3((NN + 1023) / 1024, 3), 256>>>(big2, gate, batch, gsum, pool);

    // out = pooled @ vt_W  [64,768]x[768,2304]
    zero_kernel<<<(NB * FV / 4 + 255) / 256, 256>>>((float4*)out, NB * FV / 4);
    smallgemm<<<dim3(FV / 64, FF / SGK, 1), 256>>>(pool, vt_W, out, NB, FV, FF);
}